// round 11
// baseline (speedup 1.0000x reference)
#include <cuda_runtime.h>

// Problem constants
#define B_IMG 8
#define H_IMG 1024
#define W_IMG 1024
#define HW (H_IMG * W_IMG)

#define TILE   32          // output tile 32x32
#define NT     256         // threads per block (8 warps)

// sy: luminance tile + halo 7 each side -> rows 46, cols 46, stored with
// left pad 3 (y at x(rel) stored at col x+10) so strip reads are 16B-aligned.
#define YROWS  46
#define YS     52          // stride (multiple of 4 -> row-aligned float4)
// hs: horizontal 5-sums, 36 rows (d-rows -2..33) x 32 cols, stride 36.
#define HSS    36
// rgb halo 5 each side
#define RH     42

// Scratch luminance plane (32 MiB) — static device array (allowed).
__device__ float g_y[B_IMG * HW];

// ---------------------------------------------------------------------------
// Kernel 1: y = mean(rgb, channel) — float4
// ---------------------------------------------------------------------------
__global__ void lum_kernel(const float* __restrict__ rgb) {
    int i = blockIdx.x * blockDim.x + threadIdx.x;
    const int n4 = B_IMG * HW / 4;
    if (i >= n4) return;
    const int hw4 = HW / 4;
    int b  = i / hw4;
    int p4 = i - b * hw4;
    const float4* base = reinterpret_cast<const float4*>(rgb + (size_t)b * 3 * HW) + p4;
    float4 r = base[0];
    float4 g = base[hw4];
    float4 bl = base[2 * hw4];
    float4 y;
    const float k = 1.0f / 3.0f;
    y.x = (r.x + g.x + bl.x) * k;
    y.y = (r.y + g.y + bl.y) * k;
    y.z = (r.z + g.z + bl.z) * k;
    y.w = (r.w + g.w + bl.w) * k;
    reinterpret_cast<float4*>(g_y)[i] = y;
}

// Fused stage1+2: 12 shifted y values (v), 12 invariant y values (u) ->
// 12 squared diffs -> 8 horizontal 5-sums -> 2 STS.128.
__device__ __forceinline__ void fuse12(const float* u, const float* v, float* hrow) {
    float d[12];
#pragma unroll
    for (int k = 0; k < 12; ++k) {
        float df = u[k] - v[k];
        d[k] = df * df;
    }
    float o[8];
#pragma unroll
    for (int k = 0; k < 8; ++k)
        o[k] = ((d[k] + d[k + 1]) + (d[k + 2] + d[k + 3])) + d[k + 4];
    *reinterpret_cast<float4*>(hrow)     = make_float4(o[0], o[1], o[2], o[3]);
    *reinterpret_cast<float4*>(hrow + 4) = make_float4(o[4], o[5], o[6], o[7]);
}

// ---------------------------------------------------------------------------
// Kernel 2: tiled NLM. 32x32 tile, 256 threads, 4 px/thread (4x1 vertical
// strip) in stage3. Circular boundary resolved at smem-load time via & 1023.
//
// Equivalence with reference: reference accumulates roll(rgb,s)(p) * w where
// w = exp(-sqrt(boxsum((y - roll(y,s))^2))(p)). roll(f,s)(q) = f(q-s), so the
// integrand is (y(q)-y(q-s))^2 and the rgb term is rgb(p-s). Substituting
// s' = -s over the same symmetric shift set gives exactly the gather we
// compute: d(q) = (y(q)-y(q+s'))^2 box-summed at p, acc += rgb(p+s')*w.
// ---------------------------------------------------------------------------
__global__ __launch_bounds__(NT, 4)    // force <=64 regs -> 4 blocks/SM
void nlm_kernel(const float* __restrict__ rgb, float* __restrict__ out) {
    __shared__ __align__(16) float sy[YROWS * YS];        // 2392 floats
    __shared__ __align__(16) float hsb[2][HSS * 36];      // 2 x 1296
    __shared__ float srg[2 * RH * RH];                    // R,G interleaved
    __shared__ float sb[RH * RH];                         // B

    const int tid = threadIdx.x;
    const int x0  = blockIdx.x * TILE;
    const int y0  = blockIdx.y * TILE;
    const int b   = blockIdx.z;

    // ---- load luminance halo (wrapped): rows/cols -7..38 ----
    const float* yb = g_y + (size_t)b * HW;
    for (int i = tid; i < YROWS * 46; i += NT) {
        int r = i / 46, c = i - r * 46;
        int gy = (y0 + r - 7) & (H_IMG - 1);
        int gx = (x0 + c - 7) & (W_IMG - 1);
        sy[r * YS + c + 3] = yb[gy * W_IMG + gx];
    }
    // ---- load rgb halo (wrapped): -5..36 ----
    const float* rgbb = rgb + (size_t)b * 3 * HW;
    for (int i = tid; i < RH * RH; i += NT) {
        int r = i / RH, c = i - r * RH;
        int gy = (y0 + r - 5) & (H_IMG - 1);
        int gx = (x0 + c - 5) & (W_IMG - 1);
        int o  = gy * W_IMG + gx;
        srg[2 * i]     = rgbb[o];
        srg[2 * i + 1] = rgbb[o + HW];
        sb[i]          = rgbb[o + 2 * HW];
    }
    __syncthreads();

    // ---- fused-stage setup (threads 0..143): strip of 8 hs outputs ----
    const bool fact = (tid < 144);
    const int  fh   = tid >> 2;            // hs row 0..35 (d-row fh-2)
    const int  fxs  = (tid & 3) << 3;      // 0,8,16,24
    // Invariant operand: y(d-row fh-2, cols fxs-2..fxs+9) — load ONCE.
    float uu[12];
    if (fact) {
        const float* urow = sy + (fh + 5) * YS + fxs + 8;   // 16B aligned
        *reinterpret_cast<float4*>(uu)     = *reinterpret_cast<const float4*>(urow);
        *reinterpret_cast<float4*>(uu + 4) = *reinterpret_cast<const float4*>(urow + 4);
        *reinterpret_cast<float4*>(uu + 8) = *reinterpret_cast<const float4*>(urow + 8);
    }

    // ---- stage3 setup: 4x1 vertical strip per thread ----
    const int col = tid & 31;              // output col
    const int rp  = (tid >> 5) << 2;       // output rows rp..rp+3
    const int s3h    = rp * HSS + col;
    const int robase = (rp + 5) * RH + (col + 5);

    float aR0 = 0.f, aG0 = 0.f, aB0 = 0.f, ws0 = 0.f;
    float aR1 = 0.f, aG1 = 0.f, aB1 = 0.f, ws1 = 0.f;
    float aR2 = 0.f, aG2 = 0.f, aB2 = 0.f, ws2 = 0.f;
    float aR3 = 0.f, aG3 = 0.f, aB3 = 0.f, ws3 = 0.f;
    const float inv_h = 1.0f / (1.0f + 1e-6f);

    int dy = -5, dx = -5;                  // incremental shift counters
    #pragma unroll 1
    for (int sidx = 0; sidx < 121; ++sidx) {
        float* const hsc = hsb[sidx & 1];

        // ---- fused stage1+2 ----
        if (fact) {
            const int m = dx & 3;                       // uniform across block
            // aligned base: (dx - m) is a multiple of 4
            const float* srow = sy + (fh + 5 + dy) * YS + fxs + 8 + (dx - m);
            float vv[16];
            *reinterpret_cast<float4*>(vv)      = *reinterpret_cast<const float4*>(srow);
            *reinterpret_cast<float4*>(vv + 4)  = *reinterpret_cast<const float4*>(srow + 4);
            *reinterpret_cast<float4*>(vv + 8)  = *reinterpret_cast<const float4*>(srow + 8);
            *reinterpret_cast<float4*>(vv + 12) = *reinterpret_cast<const float4*>(srow + 12);
            float* hrow = hsc + fh * HSS + fxs;
            switch (m) {                                // uniform branch
                case 0:  fuse12(uu, vv + 0, hrow); break;
                case 1:  fuse12(uu, vv + 1, hrow); break;
                case 2:  fuse12(uu, vv + 2, hrow); break;
                default: fuse12(uu, vv + 3, hrow); break;
            }
        }
        __syncthreads();
        // Double buffer makes this single barrier sufficient: stage3(i) reads
        // hsb[i&1]; the next write to that buffer is fused(i+2), which every
        // thread reaches only after sync(i+1), which follows all stage3(i).

        // ---- stage3: 4 overlapping vertical 5-sums from 8 hs rows ----
        {
            const float* p = hsc + s3h;
            float h0 = p[0],       h1 = p[HSS],     h2 = p[2*HSS], h3 = p[3*HSS];
            float h4 = p[4*HSS],   h5 = p[5*HSS],   h6 = p[6*HSS], h7 = p[7*HSS];
            float t1 = h1 + h2, t2 = h3 + h4, t3 = h5 + h6;
            float S0 = (h0 + t1) + t2;
            float S1 = (t1 + t2) + h5;
            float S2 = (h2 + t2) + t3;
            float S3 = (t2 + t3) + h7;
            float w0 = __expf(-sqrtf(S0) * inv_h);
            float w1 = __expf(-sqrtf(S1) * inv_h);
            float w2 = __expf(-sqrtf(S2) * inv_h);
            float w3 = __expf(-sqrtf(S3) * inv_h);

            int ro0 = robase + dy * RH + dx;
            int ro1 = ro0 + RH, ro2 = ro0 + 2 * RH, ro3 = ro0 + 3 * RH;
            float2 g0 = *reinterpret_cast<const float2*>(srg + 2 * ro0);
            float2 g1 = *reinterpret_cast<const float2*>(srg + 2 * ro1);
            float2 g2 = *reinterpret_cast<const float2*>(srg + 2 * ro2);
            float2 g3 = *reinterpret_cast<const float2*>(srg + 2 * ro3);
            float b0 = sb[ro0], b1 = sb[ro1], b2 = sb[ro2], b3 = sb[ro3];

            aR0 = fmaf(g0.x, w0, aR0); aG0 = fmaf(g0.y, w0, aG0);
            aB0 = fmaf(b0,   w0, aB0); ws0 += w0;
            aR1 = fmaf(g1.x, w1, aR1); aG1 = fmaf(g1.y, w1, aG1);
            aB1 = fmaf(b1,   w1, aB1); ws1 += w1;
            aR2 = fmaf(g2.x, w2, aR2); aG2 = fmaf(g2.y, w2, aG2);
            aB2 = fmaf(b2,   w2, aB2); ws2 += w2;
            aR3 = fmaf(g3.x, w3, aR3); aG3 = fmaf(g3.y, w3, aG3);
            aB3 = fmaf(b3,   w3, aB3); ws3 += w3;
        }

        // advance (dy, dx) through the 11x11 window
        if (++dx > 5) { dx = -5; ++dy; }
    }

    // ---- normalize + store 4 pixels (4 rows, same col) ----
    const float i0 = 1.0f / ws0, i1 = 1.0f / ws1;
    const float i2 = 1.0f / ws2, i3 = 1.0f / ws3;
    const size_t base0 = (size_t)b * 3 * HW + (size_t)(y0 + rp) * W_IMG + (x0 + col);
    out[base0]                      = aR0 * i0;
    out[base0 + HW]                 = aG0 * i0;
    out[base0 + 2 * HW]             = aB0 * i0;
    out[base0 + W_IMG]              = aR1 * i1;
    out[base0 + W_IMG + HW]         = aG1 * i1;
    out[base0 + W_IMG + 2 * HW]     = aB1 * i1;
    out[base0 + 2 * W_IMG]          = aR2 * i2;
    out[base0 + 2 * W_IMG + HW]     = aG2 * i2;
    out[base0 + 2 * W_IMG + 2 * HW] = aB2 * i2;
    out[base0 + 3 * W_IMG]          = aR3 * i3;
    out[base0 + 3 * W_IMG + HW]     = aG3 * i3;
    out[base0 + 3 * W_IMG + 2 * HW] = aB3 * i3;
}

// ---------------------------------------------------------------------------
extern "C" void kernel_launch(void* const* d_in, const int* in_sizes, int n_in,
                              void* d_out, int out_size) {
    const float* rgb = (const float*)d_in[0];
    float* out = (float*)d_out;

    int n4 = B_IMG * HW / 4;
    lum_kernel<<<(n4 + 255) / 256, 256>>>(rgb);

    dim3 grid(W_IMG / TILE, H_IMG / TILE, B_IMG);
    nlm_kernel<<<grid, NT>>>(rgb, out);
}

// round 12
// speedup vs baseline: 1.2257x; 1.2257x over previous
#include <cuda_runtime.h>

// Problem constants
#define B_IMG 8
#define H_IMG 1024
#define W_IMG 1024
#define HW (H_IMG * W_IMG)

#define TILE   32          // output tile 32x32
#define NT     256         // threads per block (8 warps)

// sy: luminance tile + halo 7 each side -> rows 46, cols 46, stored with
// left pad 3 (y at x(rel) stored at col x+10) so strip reads are 16B-aligned.
#define YROWS  46
#define YS     52          // stride (multiple of 4 -> row-aligned float4)
// hs: horizontal 5-sums, 36 rows (d-rows -2..33) x 32 cols, stride 36.
#define HSS    36
// rgb halo 5 each side
#define RH     42

// Scratch luminance plane (32 MiB) — static device array (allowed).
__device__ float g_y[B_IMG * HW];

// ---------------------------------------------------------------------------
// Kernel 1: y = mean(rgb, channel) — float4
// ---------------------------------------------------------------------------
__global__ void lum_kernel(const float* __restrict__ rgb) {
    int i = blockIdx.x * blockDim.x + threadIdx.x;
    const int n4 = B_IMG * HW / 4;
    if (i >= n4) return;
    const int hw4 = HW / 4;
    int b  = i / hw4;
    int p4 = i - b * hw4;
    const float4* base = reinterpret_cast<const float4*>(rgb + (size_t)b * 3 * HW) + p4;
    float4 r = base[0];
    float4 g = base[hw4];
    float4 bl = base[2 * hw4];
    float4 y;
    const float k = 1.0f / 3.0f;
    y.x = (r.x + g.x + bl.x) * k;
    y.y = (r.y + g.y + bl.y) * k;
    y.z = (r.z + g.z + bl.z) * k;
    y.w = (r.w + g.w + bl.w) * k;
    reinterpret_cast<float4*>(g_y)[i] = y;
}

// Fused stage1+2: 12 shifted y values (v, register-resident), 12 invariant y
// values (u) -> 12 squared diffs -> 8 horizontal 5-sums -> 2 STS.128.
__device__ __forceinline__ void fuse12(const float* u, const float* v, float* hrow) {
    float d[12];
#pragma unroll
    for (int k = 0; k < 12; ++k) {
        float df = u[k] - v[k];
        d[k] = df * df;
    }
    float o[8];
#pragma unroll
    for (int k = 0; k < 8; ++k)
        o[k] = ((d[k] + d[k + 1]) + (d[k + 2] + d[k + 3])) + d[k + 4];
    *reinterpret_cast<float4*>(hrow)     = make_float4(o[0], o[1], o[2], o[3]);
    *reinterpret_cast<float4*>(hrow + 4) = make_float4(o[4], o[5], o[6], o[7]);
}

// ---------------------------------------------------------------------------
// Kernel 2: tiled NLM. 32x32 tile, 256 threads, 4 px/thread (2x2) in stage3
// (the empirically-best R10 layout). dy-outer / dx-inner loop with the
// shifted luminance row cached in registers per dy (two 20-float groups).
//
// Equivalence with reference: reference accumulates roll(rgb,s)(p) * w where
// w = exp(-sqrt(boxsum((y - roll(y,s))^2))(p)). roll(f,s)(q) = f(q-s), so the
// integrand is (y(q)-y(q-s))^2 and the rgb term is rgb(p-s). Substituting
// s' = -s over the same symmetric shift set gives exactly the gather we
// compute: d(q) = (y(q)-y(q+s'))^2 box-summed at p, acc += rgb(p+s')*w.
// ---------------------------------------------------------------------------
__global__ __launch_bounds__(NT, 3)    // 85-reg cap: room for v-row caching
void nlm_kernel(const float* __restrict__ rgb, float* __restrict__ out) {
    __shared__ __align__(16) float sy[YROWS * YS];        // 2392 floats
    __shared__ __align__(16) float hsb[2][HSS * 36];      // 2 x 1296
    __shared__ float srg[2 * RH * RH];                    // R,G interleaved
    __shared__ float sb[RH * RH];                         // B

    const int tid = threadIdx.x;
    const int x0  = blockIdx.x * TILE;
    const int y0  = blockIdx.y * TILE;
    const int b   = blockIdx.z;

    // ---- load luminance halo (wrapped): rows/cols -7..38 ----
    const float* yb = g_y + (size_t)b * HW;
    for (int i = tid; i < YROWS * 46; i += NT) {
        int r = i / 46, c = i - r * 46;
        int gy = (y0 + r - 7) & (H_IMG - 1);
        int gx = (x0 + c - 7) & (W_IMG - 1);
        sy[r * YS + c + 3] = yb[gy * W_IMG + gx];
    }
    // ---- load rgb halo (wrapped): -5..36 ----
    const float* rgbb = rgb + (size_t)b * 3 * HW;
    for (int i = tid; i < RH * RH; i += NT) {
        int r = i / RH, c = i - r * RH;
        int gy = (y0 + r - 5) & (H_IMG - 1);
        int gx = (x0 + c - 5) & (W_IMG - 1);
        int o  = gy * W_IMG + gx;
        srg[2 * i]     = rgbb[o];
        srg[2 * i + 1] = rgbb[o + HW];
        sb[i]          = rgbb[o + 2 * HW];
    }
    __syncthreads();

    // ---- fused-stage setup (threads 0..143): strip of 8 hs outputs ----
    const bool fact = (tid < 144);
    const int  fh   = tid >> 2;            // hs row 0..35 (d-row fh-2)
    const int  fxs  = (tid & 3) << 3;      // 0,8,16,24
    // Invariant operand: y(d-row fh-2, cols fxs-2..fxs+9) — load ONCE.
    float uu[12];
    if (fact) {
        const float* urow = sy + (fh + 5) * YS + fxs + 8;   // 16B aligned
        *reinterpret_cast<float4*>(uu)     = *reinterpret_cast<const float4*>(urow);
        *reinterpret_cast<float4*>(uu + 4) = *reinterpret_cast<const float4*>(urow + 4);
        *reinterpret_cast<float4*>(uu + 8) = *reinterpret_cast<const float4*>(urow + 8);
    }

    // ---- stage3 setup: 2x2 output pixels per thread (R10 layout) ----
    const int cp = (tid & 15) << 1;        // cols cp, cp+1
    const int rp = (tid >> 4) << 1;        // rows rp, rp+1
    const int s3h    = rp * HSS + cp;
    const int robase = (rp + 5) * RH + (cp + 5);

    float aR00 = 0.f, aG00 = 0.f, aB00 = 0.f, w00s = 0.f;
    float aR01 = 0.f, aG01 = 0.f, aB01 = 0.f, w01s = 0.f;
    float aR10 = 0.f, aG10 = 0.f, aB10 = 0.f, w10s = 0.f;
    float aR11 = 0.f, aG11 = 0.f, aB11 = 0.f, w11s = 0.f;
    const float inv_h = 1.0f / (1.0f + 1e-6f);

#define STAGE3(HSC, DY, DX)                                                   \
    {                                                                         \
        const float* p = (HSC) + s3h;                                         \
        float2 v0 = *reinterpret_cast<const float2*>(p);                      \
        float2 v1 = *reinterpret_cast<const float2*>(p + HSS);                \
        float2 v2 = *reinterpret_cast<const float2*>(p + 2 * HSS);            \
        float2 v3 = *reinterpret_cast<const float2*>(p + 3 * HSS);            \
        float2 v4 = *reinterpret_cast<const float2*>(p + 4 * HSS);            \
        float2 v5 = *reinterpret_cast<const float2*>(p + 5 * HSS);            \
        float t1x = v1.x + v2.x, t1y = v1.y + v2.y;                           \
        float t2x = v3.x + v4.x, t2y = v3.y + v4.y;                           \
        float S0x = (v0.x + t1x) + t2x;                                       \
        float S0y = (v0.y + t1y) + t2y;                                       \
        float S1x = (t1x + t2x) + v5.x;                                       \
        float S1y = (t1y + t2y) + v5.y;                                       \
        float w00 = __expf(-sqrtf(S0x) * inv_h);                              \
        float w01 = __expf(-sqrtf(S0y) * inv_h);                              \
        float w10 = __expf(-sqrtf(S1x) * inv_h);                              \
        float w11 = __expf(-sqrtf(S1y) * inv_h);                              \
        int ro00 = robase + (DY) * RH + (DX);                                 \
        int ro10 = ro00 + RH;                                                 \
        float2 g00 = *reinterpret_cast<const float2*>(srg + 2 * ro00);        \
        float2 g01 = *reinterpret_cast<const float2*>(srg + 2 * (ro00 + 1));  \
        float2 g10 = *reinterpret_cast<const float2*>(srg + 2 * ro10);        \
        float2 g11 = *reinterpret_cast<const float2*>(srg + 2 * (ro10 + 1));  \
        float b00 = sb[ro00], b01 = sb[ro00 + 1];                             \
        float b10 = sb[ro10], b11 = sb[ro10 + 1];                             \
        aR00 = fmaf(g00.x, w00, aR00); aG00 = fmaf(g00.y, w00, aG00);         \
        aB00 = fmaf(b00,   w00, aB00); w00s += w00;                           \
        aR01 = fmaf(g01.x, w01, aR01); aG01 = fmaf(g01.y, w01, aG01);         \
        aB01 = fmaf(b01,   w01, aB01); w01s += w01;                           \
        aR10 = fmaf(g10.x, w10, aR10); aG10 = fmaf(g10.y, w10, aG10);         \
        aB10 = fmaf(b10,   w10, aB10); w10s += w10;                           \
        aR11 = fmaf(g11.x, w11, aR11); aG11 = fmaf(g11.y, w11, aG11);         \
        aB11 = fmaf(b11,   w11, aB11); w11s += w11;                           \
    }

    int sidx = 0;
    #pragma unroll 1
    for (int dy = -5; dy <= 5; ++dy) {
        // v-row for this dy: sy row fh+5+dy. vA[k] = col fxs+k (k=0..19),
        // vB[k] = col fxs+8+k (k=0..19). Aligned float4 loads; pad/garbage
        // lanes are loaded but never consumed by any window.
        const float* vrow = sy + (fh + 5 + dy) * YS + fxs;

        float vA[20];
        if (fact) {
            *reinterpret_cast<float4*>(vA)      = *reinterpret_cast<const float4*>(vrow);
            *reinterpret_cast<float4*>(vA + 4)  = *reinterpret_cast<const float4*>(vrow + 4);
            *reinterpret_cast<float4*>(vA + 8)  = *reinterpret_cast<const float4*>(vrow + 8);
            *reinterpret_cast<float4*>(vA + 12) = *reinterpret_cast<const float4*>(vrow + 12);
            *reinterpret_cast<float4*>(vA + 16) = *reinterpret_cast<const float4*>(vrow + 16);
        }
        #pragma unroll 1
        for (int dx = -5; dx <= -1; ++dx) {
            float* const hsc = hsb[sidx & 1];
            if (fact) {
                // window: sy cols fxs+8+dx .. fxs+19+dx -> vA[8+dx .. 19+dx]
                float* hrow = hsc + fh * HSS + fxs;
                switch (dx) {                       // uniform branch
                    case -5: fuse12(uu, vA + 3, hrow); break;
                    case -4: fuse12(uu, vA + 4, hrow); break;
                    case -3: fuse12(uu, vA + 5, hrow); break;
                    case -2: fuse12(uu, vA + 6, hrow); break;
                    default: fuse12(uu, vA + 7, hrow); break;
                }
            }
            __syncthreads();
            // Double buffer: stage3(i) reads hsb[i&1]; next write to that
            // buffer is fused(i+2), reached only after sync(i+1).
            STAGE3(hsc, dy, dx);
            ++sidx;
        }

        float vB[20];
        if (fact) {
            const float* vrow8 = vrow + 8;
            *reinterpret_cast<float4*>(vB)      = *reinterpret_cast<const float4*>(vrow8);
            *reinterpret_cast<float4*>(vB + 4)  = *reinterpret_cast<const float4*>(vrow8 + 4);
            *reinterpret_cast<float4*>(vB + 8)  = *reinterpret_cast<const float4*>(vrow8 + 8);
            *reinterpret_cast<float4*>(vB + 12) = *reinterpret_cast<const float4*>(vrow8 + 12);
            *reinterpret_cast<float4*>(vB + 16) = *reinterpret_cast<const float4*>(vrow8 + 16);
        }
        #pragma unroll 1
        for (int dx = 0; dx <= 5; ++dx) {
            float* const hsc = hsb[sidx & 1];
            if (fact) {
                // window: sy cols fxs+8+dx .. fxs+19+dx -> vB[dx .. dx+11]
                float* hrow = hsc + fh * HSS + fxs;
                switch (dx) {                       // uniform branch
                    case 0:  fuse12(uu, vB + 0, hrow); break;
                    case 1:  fuse12(uu, vB + 1, hrow); break;
                    case 2:  fuse12(uu, vB + 2, hrow); break;
                    case 3:  fuse12(uu, vB + 3, hrow); break;
                    case 4:  fuse12(uu, vB + 4, hrow); break;
                    default: fuse12(uu, vB + 5, hrow); break;
                }
            }
            __syncthreads();
            STAGE3(hsc, dy, dx);
            ++sidx;
        }
    }

    // ---- normalize + store 4 pixels (2x2) ----
    const float i00 = 1.0f / w00s, i01 = 1.0f / w01s;
    const float i10 = 1.0f / w10s, i11 = 1.0f / w11s;
    const size_t base0 = (size_t)b * 3 * HW + (size_t)(y0 + rp) * W_IMG + (x0 + cp);
    const size_t base1 = base0 + W_IMG;
    out[base0]              = aR00 * i00;
    out[base0 + HW]         = aG00 * i00;
    out[base0 + 2 * HW]     = aB00 * i00;
    out[base0 + 1]          = aR01 * i01;
    out[base0 + 1 + HW]     = aG01 * i01;
    out[base0 + 1 + 2 * HW] = aB01 * i01;
    out[base1]              = aR10 * i10;
    out[base1 + HW]         = aG10 * i10;
    out[base1 + 2 * HW]     = aB10 * i10;
    out[base1 + 1]          = aR11 * i11;
    out[base1 + 1 + HW]     = aG11 * i11;
    out[base1 + 1 + 2 * HW] = aB11 * i11;
}

// ---------------------------------------------------------------------------
extern "C" void kernel_launch(void* const* d_in, const int* in_sizes, int n_in,
                              void* d_out, int out_size) {
    const float* rgb = (const float*)d_in[0];
    float* out = (float*)d_out;

    int n4 = B_IMG * HW / 4;
    lum_kernel<<<(n4 + 255) / 256, 256>>>(rgb);

    dim3 grid(W_IMG / TILE, H_IMG / TILE, B_IMG);
    nlm_kernel<<<grid, NT>>>(rgb, out);
}

// round 16
// speedup vs baseline: 1.8144x; 1.4803x over previous
#include <cuda_runtime.h>

// Problem constants
#define B_IMG 8
#define H_IMG 1024
#define W_IMG 1024
#define HW (H_IMG * W_IMG)

#define TILE   32          // output tile 32x32
#define NT     256         // threads per block (8 warps)

// sy: luminance tile + halo 7 each side -> rows 46, cols 46, stored with
// left pad 3 (y at x_rel stored at col x_rel+10) so strip reads are aligned.
#define YROWS  46
#define YS     52          // stride (multiple of 4 -> row-aligned float4)
// hs: horizontal 5-sums, 36 rows x 32 cols, stride 36. 4 buffers (2 parities x 2 slots).
#define HSS    36
#define HSZ    (HSS * 36)  // 1296
// rgb halo 5 each side
#define RH     42

// Dynamic smem layout (float offsets)
#define SY_OFF   0                        // 2392
#define HS_OFF   2392                     // 4 x 1296 = 5184
#define SRG_OFF  (2392 + 4*1296)          // 7576 : 2*1764
#define SB_OFF   (7576 + 2*1764)          // 11104 : 1764
#define SMEM_FLOATS (11104 + 1764)        // 12868
#define SMEM_BYTES  (SMEM_FLOATS * 4)     // 51472

// Scratch luminance plane (32 MiB) — static device array (allowed).
__device__ float g_y[B_IMG * HW];

// ---------------------------------------------------------------------------
// Kernel 1: y = mean(rgb, channel) — float4
// ---------------------------------------------------------------------------
__global__ void lum_kernel(const float* __restrict__ rgb) {
    int i = blockIdx.x * blockDim.x + threadIdx.x;
    const int n4 = B_IMG * HW / 4;
    if (i >= n4) return;
    const int hw4 = HW / 4;
    int b  = i / hw4;
    int p4 = i - b * hw4;
    const float4* base = reinterpret_cast<const float4*>(rgb + (size_t)b * 3 * HW) + p4;
    float4 r = base[0];
    float4 g = base[hw4];
    float4 bl = base[2 * hw4];
    float4 y;
    const float k = 1.0f / 3.0f;
    y.x = (r.x + g.x + bl.x) * k;
    y.y = (r.y + g.y + bl.y) * k;
    y.z = (r.z + g.z + bl.z) * k;
    y.w = (r.w + g.w + bl.w) * k;
    reinterpret_cast<float4*>(g_y)[i] = y;
}

// Fused stage1+2: 12 shifted y values (v) vs 12 invariant y values (u) ->
// 12 squared diffs -> 8 horizontal 5-sums -> 2 STS.128.
__device__ __forceinline__ void fuse12(const float* u, const float* v, float* hrow) {
    float d[12];
#pragma unroll
    for (int k = 0; k < 12; ++k) {
        float df = u[k] - v[k];
        d[k] = df * df;
    }
    float o[8];
#pragma unroll
    for (int k = 0; k < 8; ++k)
        o[k] = ((d[k] + d[k + 1]) + (d[k + 2] + d[k + 3])) + d[k + 4];
    *reinterpret_cast<float4*>(hrow)     = make_float4(o[0], o[1], o[2], o[3]);
    *reinterpret_cast<float4*>(hrow + 4) = make_float4(o[4], o[5], o[6], o[7]);
}

// ---------------------------------------------------------------------------
// Kernel 2: tiled NLM. 32x32 tile, 256 threads, 4 px/thread (2x2, the proven
// R10 stage-3 layout). TWO dx shifts per barrier interval: one 16-float
// aligned v-load feeds both 12-wide windows (vv+m, vv+m+1). 66 barriers.
//
// Equivalence with reference: reference accumulates roll(rgb,s)(p) * w where
// w = exp(-sqrt(boxsum((y - roll(y,s))^2))(p)). roll(f,s)(q) = f(q-s);
// substituting s' = -s over the same symmetric shift set gives the gather we
// compute: d(q) = (y(q)-y(q+s'))^2 box-summed at p, acc += rgb(p+s')*w.
// ---------------------------------------------------------------------------
__global__ __launch_bounds__(NT, 4)    // hold 4 blocks/SM: <=64 regs
void nlm_kernel(const float* __restrict__ rgb, float* __restrict__ out) {
    extern __shared__ __align__(16) float smem[];
    float* const sy  = smem + SY_OFF;
    float* const hs0 = smem + HS_OFF;            // 4 buffers of HSZ
    float* const srg = smem + SRG_OFF;           // R,G interleaved
    float* const sb  = smem + SB_OFF;            // B

    const int tid = threadIdx.x;
    const int x0  = blockIdx.x * TILE;
    const int y0  = blockIdx.y * TILE;
    const int b   = blockIdx.z;

    // ---- load luminance halo (wrapped): rows/cols -7..38 ----
    const float* yb = g_y + (size_t)b * HW;
    for (int i = tid; i < YROWS * 46; i += NT) {
        int r = i / 46, c = i - r * 46;
        int gy = (y0 + r - 7) & (H_IMG - 1);
        int gx = (x0 + c - 7) & (W_IMG - 1);
        sy[r * YS + c + 3] = yb[gy * W_IMG + gx];
    }
    // ---- load rgb halo (wrapped): -5..36 ----
    const float* rgbb = rgb + (size_t)b * 3 * HW;
    for (int i = tid; i < RH * RH; i += NT) {
        int r = i / RH, c = i - r * RH;
        int gy = (y0 + r - 5) & (H_IMG - 1);
        int gx = (x0 + c - 5) & (W_IMG - 1);
        int o  = gy * W_IMG + gx;
        srg[2 * i]     = rgbb[o];
        srg[2 * i + 1] = rgbb[o + HW];
        sb[i]          = rgbb[o + 2 * HW];
    }
    __syncthreads();

    // ---- fused-stage setup (threads 0..143): strip of 8 hs outputs ----
    const bool fact = (tid < 144);
    const int  fh   = tid >> 2;            // hs row 0..35 (d-row fh-2)
    const int  fxs  = (tid & 3) << 3;      // 0,8,16,24
    const int  hrow_off = fh * HSS + fxs;
    // Invariant operand: y(d-row fh-2, x_rel fxs-2..fxs+9) — load ONCE.
    float uu[12];
    if (fact) {
        const float* urow = sy + (fh + 5) * YS + fxs + 8;   // 16B aligned
        *reinterpret_cast<float4*>(uu)     = *reinterpret_cast<const float4*>(urow);
        *reinterpret_cast<float4*>(uu + 4) = *reinterpret_cast<const float4*>(urow + 4);
        *reinterpret_cast<float4*>(uu + 8) = *reinterpret_cast<const float4*>(urow + 8);
    }

    // ---- stage3 setup: 2x2 output pixels per thread ----
    const int cp = (tid & 15) << 1;        // cols cp, cp+1
    const int rp = (tid >> 4) << 1;        // rows rp, rp+1
    const int s3h    = rp * HSS + cp;
    const int robase = (rp + 5) * RH + (cp + 5);

    float aR00 = 0.f, aG00 = 0.f, aB00 = 0.f, w00s = 0.f;
    float aR01 = 0.f, aG01 = 0.f, aB01 = 0.f, w01s = 0.f;
    float aR10 = 0.f, aG10 = 0.f, aB10 = 0.f, w10s = 0.f;
    float aR11 = 0.f, aG11 = 0.f, aB11 = 0.f, w11s = 0.f;
    const float inv_h = 1.0f / (1.0f + 1e-6f);

#define STAGE3(HSC, DY, DX)                                                   \
    {                                                                         \
        const float* p = (HSC) + s3h;                                         \
        float2 v0 = *reinterpret_cast<const float2*>(p);                      \
        float2 v1 = *reinterpret_cast<const float2*>(p + HSS);                \
        float2 v2 = *reinterpret_cast<const float2*>(p + 2 * HSS);            \
        float2 v3 = *reinterpret_cast<const float2*>(p + 3 * HSS);            \
        float2 v4 = *reinterpret_cast<const float2*>(p + 4 * HSS);            \
        float2 v5 = *reinterpret_cast<const float2*>(p + 5 * HSS);            \
        float t1x = v1.x + v2.x, t1y = v1.y + v2.y;                           \
        float t2x = v3.x + v4.x, t2y = v3.y + v4.y;                           \
        float S0x = (v0.x + t1x) + t2x;                                       \
        float S0y = (v0.y + t1y) + t2y;                                       \
        float S1x = (t1x + t2x) + v5.x;                                       \
        float S1y = (t1y + t2y) + v5.y;                                       \
        float w00 = __expf(-sqrtf(S0x) * inv_h);                              \
        float w01 = __expf(-sqrtf(S0y) * inv_h);                              \
        float w10 = __expf(-sqrtf(S1x) * inv_h);                              \
        float w11 = __expf(-sqrtf(S1y) * inv_h);                              \
        int ro00 = robase + (DY) * RH + (DX);                                 \
        int ro10 = ro00 + RH;                                                 \
        float2 g00 = *reinterpret_cast<const float2*>(srg + 2 * ro00);        \
        float2 g01 = *reinterpret_cast<const float2*>(srg + 2 * (ro00 + 1));  \
        float2 g10 = *reinterpret_cast<const float2*>(srg + 2 * ro10);        \
        float2 g11 = *reinterpret_cast<const float2*>(srg + 2 * (ro10 + 1));  \
        float b00 = sb[ro00], b01 = sb[ro00 + 1];                             \
        float b10 = sb[ro10], b11 = sb[ro10 + 1];                             \
        aR00 = fmaf(g00.x, w00, aR00); aG00 = fmaf(g00.y, w00, aG00);         \
        aB00 = fmaf(b00,   w00, aB00); w00s += w00;                           \
        aR01 = fmaf(g01.x, w01, aR01); aG01 = fmaf(g01.y, w01, aG01);         \
        aB01 = fmaf(b01,   w01, aB01); w01s += w01;                           \
        aR10 = fmaf(g10.x, w10, aR10); aG10 = fmaf(g10.y, w10, aG10);         \
        aB10 = fmaf(b10,   w10, aB10); w10s += w10;                           \
        aR11 = fmaf(g11.x, w11, aR11); aG11 = fmaf(g11.y, w11, aG11);         \
        aB11 = fmaf(b11,   w11, aB11); w11s += w11;                           \
    }

#define LOADVV(SROW)                                                          \
    *reinterpret_cast<float4*>(vv)      = *reinterpret_cast<const float4*>(SROW);      \
    *reinterpret_cast<float4*>(vv + 4)  = *reinterpret_cast<const float4*>((SROW) + 4); \
    *reinterpret_cast<float4*>(vv + 8)  = *reinterpret_cast<const float4*>((SROW) + 8); \
    *reinterpret_cast<float4*>(vv + 12) = *reinterpret_cast<const float4*>((SROW) + 12);

    int ip = 0;   // interval parity (selects buffer pair)
    #pragma unroll 1
    for (int dy = -5; dy <= 5; ++dy) {
        // Column of the dx=0 window start in this thread's sy row.
        const float* vbase = sy + (fh + 5 + dy) * YS + fxs + 8;

        // ---- singleton interval: dx = -5 (m=3 -> load base -8, window vv+3)
        {
            float* const hA = hs0 + (ip << 1) * HSZ;
            if (fact) {
                float vv[16];
                LOADVV(vbase - 8);
                fuse12(uu, vv + 3, hA + hrow_off);
            }
            __syncthreads();
            STAGE3(hA, dy, -5);
            ip ^= 1;
        }

        // ---- 5 pair intervals: dxb in {-4,-2,0,2,4}; m = dxb&3 in {0,2} ----
        #pragma unroll 1
        for (int dxb = -4; dxb <= 4; dxb += 2) {
            float* const hA = hs0 + (ip << 1) * HSZ;
            float* const hB = hA + HSZ;
            if (fact) {
                const int m = dxb & 3;                  // uniform: 0 or 2
                float vv[16];
                LOADVV(vbase + (dxb - m));
                if (m == 0) {                           // uniform branch
                    fuse12(uu, vv + 0, hA + hrow_off);
                    fuse12(uu, vv + 1, hB + hrow_off);
                } else {
                    fuse12(uu, vv + 2, hA + hrow_off);
                    fuse12(uu, vv + 3, hB + hrow_off);
                }
            }
            __syncthreads();
            // Buffer safety: these reads are of parity ip; next writes to
            // parity ip occur two intervals later, after the next sync.
            STAGE3(hA, dy, dxb);
            STAGE3(hB, dy, dxb + 1);
            ip ^= 1;
        }
    }

    // ---- normalize + store 4 pixels (2x2) ----
    const float i00 = 1.0f / w00s, i01 = 1.0f / w01s;
    const float i10 = 1.0f / w10s, i11 = 1.0f / w11s;
    const size_t base0 = (size_t)b * 3 * HW + (size_t)(y0 + rp) * W_IMG + (x0 + cp);
    const size_t base1 = base0 + W_IMG;
    out[base0]              = aR00 * i00;
    out[base0 + HW]         = aG00 * i00;
    out[base0 + 2 * HW]     = aB00 * i00;
    out[base0 + 1]          = aR01 * i01;
    out[base0 + 1 + HW]     = aG01 * i01;
    out[base0 + 1 + 2 * HW] = aB01 * i01;
    out[base1]              = aR10 * i10;
    out[base1 + HW]         = aG10 * i10;
    out[base1 + 2 * HW]     = aB10 * i10;
    out[base1 + 1]          = aR11 * i11;
    out[base1 + 1 + HW]     = aG11 * i11;
    out[base1 + 1 + 2 * HW] = aB11 * i11;
}

// ---------------------------------------------------------------------------
extern "C" void kernel_launch(void* const* d_in, const int* in_sizes, int n_in,
                              void* d_out, int out_size) {
    const float* rgb = (const float*)d_in[0];
    float* out = (float*)d_out;

    // Function attribute only (no allocation) — legal under capture.
    cudaFuncSetAttribute(nlm_kernel,
                         cudaFuncAttributeMaxDynamicSharedMemorySize,
                         SMEM_BYTES);

    int n4 = B_IMG * HW / 4;
    lum_kernel<<<(n4 + 255) / 256, 256>>>(rgb);

    dim3 grid(W_IMG / TILE, H_IMG / TILE, B_IMG);
    nlm_kernel<<<grid, NT, SMEM_BYTES>>>(rgb, out);
}